// round 1
// baseline (speedup 1.0000x reference)
#include <cuda_runtime.h>

// Problem constants (fixed shapes)
#define Tt 2048
#define Bb 8
#define Dd 512
#define Ss 4
#define GHh 64

// ---------------- scratch (static device globals; no runtime alloc) ----------------
__device__ float g_preds[(size_t)Bb*Tt*Ss*Dd];   // layout [t][b][s][d]
__device__ float g_wenc [(size_t)Bb*Tt*Ss*Dd];   // layout [t][b][s][d]
__device__ float g_hpart[(size_t)Bb*Tt*Ss*GHh];  // layout [t][b][s][h]
__device__ float g_err  [Tt*Bb*Ss];              // [t][b][s]
__device__ float g_em   [Tt*Ss];
__device__ float g_mu   [Tt*Ss];                 // carry value at step t
__device__ float g_dv   [Tt*Ss];
__device__ float g_sig  [Tt*Ss];                 // carry value at step t
__device__ float g_gall [3*Tt*Bb*Ss];            // [st][t][b][s]
__device__ float g_gmean[3*Tt*Ss];               // [st][t][s]
__device__ int   g_state[Tt*Ss];                 // state used at step t
__device__ float g_ge   [Tt*Bb*Ss];              // effective gate [t][b][s]
__device__ float g_seb  [3*Ss*GHh];              // state-embed contribution (w/o b1)

// ---------------- seb: state_embed @ gate_W1[513:521] ----------------
__global__ void seb_kernel(const float* __restrict__ gate_W1,
                           const float* __restrict__ state_embed) {
    int i = blockIdx.x * blockDim.x + threadIdx.x;
    if (i >= 3 * Ss * GHh) return;
    int h = i % GHh;
    int s = (i / GHh) % Ss;
    int st = i / (GHh * Ss);
    float acc = 0.f;
#pragma unroll
    for (int e = 0; e < 8; e++)
        acc += state_embed[st * 8 + e] * gate_W1[((size_t)s * 521 + 513 + e) * GHh + h];
    g_seb[i] = acc;
}

// ---------------- fp32 SIMT GEMM, per-slot B, row remap (b*T+t) -> (t*B+b) --------
template<int BM, int BN, int BK, int TM, int TN>
__global__ void __launch_bounds__((BM/TM)*(BN/TN))
sgemm_kernel(const float* __restrict__ A, const float* __restrict__ Bbase,
             long bSlotStride, int ldb, const float* __restrict__ biasBase,
             float* __restrict__ outBase, int N, int K) {
    constexpr int NT = (BM/TM)*(BN/TN);
    const int s = blockIdx.z;
    const float* Bm   = Bbase + (long)s * bSlotStride;
    const float* bias = biasBase + (long)s * N;
    float* out        = outBase + (long)s * N;
    const int orstride = Ss * N;

    __shared__ float As[BK][BM];
    __shared__ float Bs[BK][BN];
    const int tid = threadIdx.x;
    const int rowBlock = blockIdx.y * BM;
    const int colBlock = blockIdx.x * BN;
    const int tcol = tid % (BN/TN);
    const int trow = tid / (BN/TN);

    float acc[TM][TN];
#pragma unroll
    for (int i = 0; i < TM; i++)
#pragma unroll
        for (int j = 0; j < TN; j++) acc[i][j] = 0.f;

    for (int k0 = 0; k0 < K; k0 += BK) {
#pragma unroll
        for (int i = tid; i < BM*BK/4; i += NT) {
            int r = i / (BK/4), c = i % (BK/4);
            float4 v = *(const float4*)&A[(long)(rowBlock + r) * K + k0 + c*4];
            As[c*4+0][r] = v.x; As[c*4+1][r] = v.y;
            As[c*4+2][r] = v.z; As[c*4+3][r] = v.w;
        }
#pragma unroll
        for (int i = tid; i < BK*BN/4; i += NT) {
            int r = i / (BN/4), c = i % (BN/4);
            *(float4*)&Bs[r][c*4] =
                *(const float4*)&Bm[(long)(k0 + r) * ldb + colBlock + c*4];
        }
        __syncthreads();
#pragma unroll
        for (int kk = 0; kk < BK; kk++) {
            float ra[TM], rb[TN];
#pragma unroll
            for (int i = 0; i < TM; i += 4) {
                float4 v = *(float4*)&As[kk][trow*TM + i];
                ra[i] = v.x; ra[i+1] = v.y; ra[i+2] = v.z; ra[i+3] = v.w;
            }
#pragma unroll
            for (int j = 0; j < TN; j += 4) {
                float4 v = *(float4*)&Bs[kk][tcol*TN + j];
                rb[j] = v.x; rb[j+1] = v.y; rb[j+2] = v.z; rb[j+3] = v.w;
            }
#pragma unroll
            for (int i = 0; i < TM; i++)
#pragma unroll
                for (int j = 0; j < TN; j++)
                    acc[i][j] += ra[i] * rb[j];
        }
        __syncthreads();
    }

#pragma unroll
    for (int i = 0; i < TM; i++) {
        int r = rowBlock + trow*TM + i;   // r = b*T + t
        int t = r & (Tt - 1);
        int b = r >> 11;                  // T = 2048
        long orow = (long)(t * Bb + b) * orstride;
#pragma unroll
        for (int j = 0; j < TN; j += 4) {
            int col = colBlock + tcol*TN + j;
            float4 v;
            v.x = acc[i][j]   + bias[col];
            v.y = acc[i][j+1] + bias[col+1];
            v.z = acc[i][j+2] + bias[col+2];
            v.w = acc[i][j+3] + bias[col+3];
            *(float4*)&out[orow + col] = v;
        }
    }
}

// ---------------- err[t][b][s] = ||pred[t-1] - h[t]|| ----------------
__global__ void err_kernel(const float* __restrict__ h) {
    int t = blockIdx.x, b = blockIdx.y;
    int tid = threadIdx.x;
    if (t == 0) { if (tid < Ss) g_err[b * Ss + tid] = 0.f; return; }
    float4 hh = *(const float4*)&h[((long)b * Tt + t) * Dd + tid * 4];
    __shared__ float red[4];
    int lane = tid & 31, w = tid >> 5;
    for (int s = 0; s < Ss; s++) {
        const float4* pv =
            (const float4*)&g_preds[(((long)(t-1) * Bb + b) * Ss + s) * Dd];
        float4 p = pv[tid];
        float dx = p.x - hh.x, dy = p.y - hh.y, dz = p.z - hh.z, dw = p.w - hh.w;
        float a = dx*dx + dy*dy + dz*dz + dw*dw;
#pragma unroll
        for (int o = 16; o > 0; o >>= 1) a += __shfl_xor_sync(0xffffffffu, a, o);
        if (lane == 0) red[w] = a;
        __syncthreads();
        if (tid == 0) {
            float tot = red[0] + red[1] + red[2] + red[3];
            g_err[(t * Bb + b) * Ss + s] = sqrtf(tot + 1e-8f);
        }
        __syncthreads();
    }
}

// ---------------- batch means (lane = b*4+s; reduce over b via xor 4,8,16) --------
__global__ void em_kernel() {
    int t = blockIdx.x, lane = threadIdx.x;
    float e = g_err[t * 32 + lane];
#pragma unroll
    for (int o = 4; o < 32; o <<= 1) e += __shfl_xor_sync(0xffffffffu, e, o);
    if (lane < Ss) g_em[t * Ss + lane] = e * 0.125f;
}

__global__ void mu_chain() {
    int s = threadIdx.x; if (s >= Ss) return;
    float mu = 0.f;
#pragma unroll 8
    for (int t = 0; t < Tt; t++) {
        g_mu[t * Ss + s] = mu;                 // carry value used at step t
        float e = g_em[t * Ss + s];
        if (t > 0) mu = 0.99f * mu + 0.01f * e;
    }
}

__global__ void dev_kernel() {
    int t = blockIdx.x, lane = threadIdx.x;
    int s = lane & 3;
    float e = g_err[t * 32 + lane];
    float d = fabsf(e - g_mu[t * Ss + s]);
#pragma unroll
    for (int o = 4; o < 32; o <<= 1) d += __shfl_xor_sync(0xffffffffu, d, o);
    if (lane < Ss) g_dv[t * Ss + lane] = d * 0.125f;
}

__global__ void sigma_chain() {
    int s = threadIdx.x; if (s >= Ss) return;
    float sg = 1.f;
#pragma unroll 8
    for (int t = 0; t < Tt; t++) {
        g_sig[t * Ss + s] = sg;
        float d = g_dv[t * Ss + s];
        if (t > 0) sg = 0.99f * sg + 0.01f * d;
    }
}

// ---------------- gate MLP, speculated over all 3 states ----------------
__global__ void gall_kernel(const float* __restrict__ gate_W1,
                            const float* __restrict__ gate_W2,
                            const float* __restrict__ gate_b2) {
    int t = blockIdx.x, b = blockIdx.y;
    int w = threadIdx.x >> 5, lane = threadIdx.x & 31;
    int st = w >> 2, s = w & 3;                 // 12 warps: (st, s)
    long row = ((long)t * Bb + b) * Ss + s;     // = t*32 + b*4 + s
    float z = (g_err[row] - g_mu[t * Ss + s]) / fmaxf(g_sig[t * Ss + s], 1e-3f);
    const float* hp = &g_hpart[row * GHh];
    float w1z0 = gate_W1[((size_t)s * 521 + 512) * GHh + lane];
    float w1z1 = gate_W1[((size_t)s * 521 + 512) * GHh + lane + 32];
    const float* seb = &g_seb[(st * Ss + s) * GHh];
    float v0 = hp[lane]      + z * w1z0 + seb[lane];        // hpart already has b1
    float v1 = hp[lane + 32] + z * w1z1 + seb[lane + 32];
    float a = fmaxf(v0, 0.f) * gate_W2[s * GHh + lane]
            + fmaxf(v1, 0.f) * gate_W2[s * GHh + lane + 32];
#pragma unroll
    for (int o = 16; o > 0; o >>= 1) a += __shfl_xor_sync(0xffffffffu, a, o);
    if (lane == 0) {
        float x = a + gate_b2[s];
        g_gall[(size_t)st * (Tt * Bb * Ss) + row] = 1.f / (1.f + expf(-x));
    }
}

__global__ void gmean_kernel() {
    int t = blockIdx.x, st = blockIdx.y, lane = threadIdx.x;
    float g = g_gall[(size_t)st * (Tt * Bb * Ss) + t * 32 + lane];
#pragma unroll
    for (int o = 4; o < 32; o <<= 1) g += __shfl_xor_sync(0xffffffffu, g, o);
    if (lane < Ss) g_gmean[st * Tt * Ss + t * Ss + lane] = g * 0.125f;
}

// ---------------- the one remaining sequential chain: state machine ----------------
__global__ void gate_chain() {
    int s = threadIdx.x; if (s >= Ss) return;
    float ema = 0.5f; int st = 0;
#pragma unroll 4
    for (int t = 0; t < Tt; t++) {
        g_state[t * Ss + s] = st;
        float g0 = g_gmean[0 * Tt * Ss + t * Ss + s];
        float g1 = g_gmean[1 * Tt * Ss + t * Ss + s];
        float g2 = g_gmean[2 * Tt * Ss + t * Ss + s];
        float gm = (st == 0) ? g0 : ((st == 1) ? g1 : g2);
        ema = 0.99f * ema + 0.01f * gm;
        int ns = st;
        if (st == 0) { if (ema < 0.1f) ns = 1; }
        else if (st == 1) { if (ema < 0.03f) ns = 2; else if (ema > 0.25f) ns = 0; }
        else { if (ema > 0.25f) ns = 0; }
        st = ns;
    }
}

__global__ void ge_kernel() {
    int t = blockIdx.x, lane = threadIdx.x;
    int s = lane & 3;
    int st = g_state[t * Ss + s];
    float gain = (st == 0) ? 1.0f : ((st == 1) ? 0.5f : 0.1f);
    g_ge[t * 32 + lane] = g_gall[(size_t)st * (Tt * Bb * Ss) + t * 32 + lane] * gain;
}

// ---------------- m-scan: 128 independent warps, each one (b,s,d-chunk) -----------
__global__ void mscan_kernel(const float* __restrict__ w0, float* __restrict__ out) {
    int bid = blockIdx.x;                 // 8*4*4 = 128
    int chunk = bid & 3, s = (bid >> 2) & 3, b = bid >> 4;
    int lane = threadIdx.x;
    int d = chunk * 128 + lane * 4;
    float4 m = *(const float4*)&w0[s * Dd + d];
    const float* gep = &g_ge[b * 4 + s];
    const float4* wp = (const float4*)&g_wenc[((long)b * Ss + s) * Dd + d];
    float4* op = (float4*)&out[((long)b * Tt) * (Ss * Dd) + s * Dd + d];
    const long wstride = (long)Bb * Ss * Dd / 4;   // per-t stride in float4
    const long ostride = Ss * Dd / 4;
#pragma unroll 4
    for (int t = 0; t < Tt; t++) {
        float ge = __ldg(&gep[t * 32]);
        float om = 1.f - ge;
        float4 w = wp[t * wstride];
        m.x = om * m.x + ge * w.x;
        m.y = om * m.y + ge * w.y;
        m.z = om * m.z + ge * w.z;
        m.w = om * m.w + ge * w.w;
        op[t * ostride] = m;
    }
}

// ---------------- launch ----------------
extern "C" void kernel_launch(void* const* d_in, const int* in_sizes, int n_in,
                              void* d_out, int out_size) {
    const float* h_seq       = (const float*)d_in[0];
    const float* pred_W      = (const float*)d_in[1];
    const float* pred_b      = (const float*)d_in[2];
    const float* gate_W1     = (const float*)d_in[3];
    const float* gate_b1     = (const float*)d_in[4];
    const float* gate_W2     = (const float*)d_in[5];
    const float* gate_b2     = (const float*)d_in[6];
    const float* write_W     = (const float*)d_in[7];
    const float* write_b     = (const float*)d_in[8];
    const float* w0          = (const float*)d_in[9];
    const float* state_embed = (const float*)d_in[10];
    float* out = (float*)d_out;

    float *p_preds, *p_wenc, *p_hpart;
    cudaGetSymbolAddress((void**)&p_preds, g_preds);
    cudaGetSymbolAddress((void**)&p_wenc,  g_wenc);
    cudaGetSymbolAddress((void**)&p_hpart, g_hpart);

    seb_kernel<<<3, 256>>>(gate_W1, state_embed);

    dim3 gBig(Dd / 128, (Bb * Tt) / 128, Ss);
    sgemm_kernel<128,128,8,8,8><<<gBig, 256>>>(h_seq, pred_W,
        (long)Dd * Dd, Dd, pred_b, p_preds, Dd, Dd);
    sgemm_kernel<128,128,8,8,8><<<gBig, 256>>>(h_seq, write_W,
        (long)Dd * Dd, Dd, write_b, p_wenc, Dd, Dd);
    dim3 gGate(1, (Bb * Tt) / 128, Ss);
    sgemm_kernel<128,64,8,8,4><<<gGate, 256>>>(h_seq, gate_W1,
        (long)521 * GHh, GHh, gate_b1, p_hpart, GHh, Dd);

    err_kernel<<<dim3(Tt, Bb), 128>>>(h_seq);
    em_kernel<<<Tt, 32>>>();
    mu_chain<<<1, 32>>>();
    dev_kernel<<<Tt, 32>>>();
    sigma_chain<<<1, 32>>>();
    gall_kernel<<<dim3(Tt, Bb), 384>>>(gate_W1, gate_W2, gate_b2);
    gmean_kernel<<<dim3(Tt, 3), 32>>>();
    gate_chain<<<1, 32>>>();
    ge_kernel<<<Tt, 32>>>();
    mscan_kernel<<<128, 32>>>(w0, out);
}

// round 3
// speedup vs baseline: 1.4674x; 1.4674x over previous
#include <cuda_runtime.h>
#include <cuda_bf16.h>
#include <cstdint>

// Problem constants (fixed shapes)
#define Tt 2048
#define Bb 8
#define Dd 512
#define Ss 4
#define GHh 64

// ---------------- scratch (static device globals; no runtime alloc) ----------------
__device__ float g_preds[(size_t)Bb*Tt*Ss*Dd];   // layout [t][b][s][d]
__device__ float g_wenc [(size_t)Bb*Tt*Ss*Dd];   // layout [t][b][s][d]
__device__ float g_hpart[(size_t)Bb*Tt*Ss*GHh];  // layout [t][b][s][h]
__device__ float g_err  [Tt*Bb*Ss];              // [t][b][s]
__device__ float g_em   [Tt*Ss];
__device__ float g_mu   [Tt*Ss];
__device__ float g_dv   [Tt*Ss];
__device__ float g_sig  [Tt*Ss];
__device__ float g_gall [3*Tt*Bb*Ss];            // [st][t][b][s]
__device__ float g_gmean[3*Tt*Ss];
__device__ int   g_state[Tt*Ss];
__device__ float g_ge   [Tt*Bb*Ss];
__device__ float g_seb  [3*Ss*GHh];

// bf16 hi/lo split operands for tensor-core GEMMs
__device__ __nv_bfloat16 g_Ahi[(size_t)Bb*Tt*Dd];
__device__ __nv_bfloat16 g_Alo[(size_t)Bb*Tt*Dd];
__device__ __nv_bfloat16 g_PWhi[Ss*Dd*Dd],  g_PWlo[Ss*Dd*Dd];    // pred_W^T [s][n][k]
__device__ __nv_bfloat16 g_WWhi[Ss*Dd*Dd],  g_WWlo[Ss*Dd*Dd];    // write_W^T
__device__ __nv_bfloat16 g_GWhi[Ss*GHh*Dd], g_GWlo[Ss*GHh*Dd];   // gate_W1[0:512]^T

// ======================= portable PTX helpers (sm_80-level) =======================
__device__ __forceinline__ uint32_t smem_u32(const void* p) {
    uint32_t a;
    asm("{ .reg .u64 t; cvta.to.shared.u64 t, %1; cvt.u32.u64 %0, t; }" : "=r"(a) : "l"(p));
    return a;
}
#define CP_ASYNC16(dst, src) \
    asm volatile("cp.async.cg.shared.global [%0], [%1], 16;" :: "r"(dst), "l"(src))
#define CP_COMMIT() asm volatile("cp.async.commit_group;" ::: "memory")
#define CP_WAIT(n)  asm volatile("cp.async.wait_group %0;" :: "n"(n) : "memory")

__device__ __forceinline__ void ldsm_x4(uint32_t* r, uint32_t addr) {
    asm volatile("ldmatrix.sync.aligned.m8n8.x4.shared.b16 {%0,%1,%2,%3}, [%4];"
        : "=r"(r[0]), "=r"(r[1]), "=r"(r[2]), "=r"(r[3]) : "r"(addr));
}
__device__ __forceinline__ void mma16816(float* d, const uint32_t* a, const uint32_t* b) {
    asm volatile("mma.sync.aligned.m16n8k16.row.col.f32.bf16.bf16.f32 "
        "{%0,%1,%2,%3}, {%4,%5,%6,%7}, {%8,%9}, {%0,%1,%2,%3};"
        : "+f"(d[0]), "+f"(d[1]), "+f"(d[2]), "+f"(d[3])
        : "r"(a[0]), "r"(a[1]), "r"(a[2]), "r"(a[3]), "r"(b[0]), "r"(b[1]));
}
__device__ __forceinline__ uint32_t sw128(uint32_t bo) { return bo ^ ((bo >> 3) & 0x70); }

// ======================= conversion pre-passes =======================
__global__ void convert_h_kernel(const float* __restrict__ h,
                                 __nv_bfloat16* __restrict__ hi,
                                 __nv_bfloat16* __restrict__ lo) {
    size_t i = (size_t)blockIdx.x * 256 + threadIdx.x;
    float v = h[i];
    __nv_bfloat16 a = __float2bfloat16(v);
    hi[i] = a;
    lo[i] = __float2bfloat16(v - __bfloat162float(a));
}

// src [S][K=512 rows][N cols] -> dst [S][N rows][512 cols] hi/lo bf16
__global__ void transpose_conv_kernel(const float* __restrict__ src, long sStride, int N,
                                      __nv_bfloat16* __restrict__ dhi,
                                      __nv_bfloat16* __restrict__ dlo) {
    __shared__ float tile[32][33];
    int s = blockIdx.z;
    int n0 = blockIdx.x * 32, k0 = blockIdx.y * 32;
    const float* sp = src + (size_t)s * sStride;
    for (int i = threadIdx.y; i < 32; i += 8)
        tile[i][threadIdx.x] = sp[(size_t)(k0 + i) * N + n0 + threadIdx.x];
    __syncthreads();
    size_t dbase = (size_t)s * N * 512;
    for (int i = threadIdx.y; i < 32; i += 8) {
        float v = tile[threadIdx.x][i];            // src[k0+tx][n0+i]
        __nv_bfloat16 h = __float2bfloat16(v);
        float lo = v - __bfloat162float(h);
        size_t off = dbase + (size_t)(n0 + i) * 512 + k0 + threadIdx.x;
        dhi[off] = h;
        dlo[off] = __float2bfloat16(lo);
    }
}

// ======================= mma.sync GEMM (bf16 hi/lo x3, fp32 accum) =======================
// C[m,n] = sum_k A[m,k] * B^T[n,k] + bias ; out row remap (b*T+t) -> (t*B+b)
// Smem tiles: 128-byte rows (64 bf16 of K), SW128 xor swizzle.
template<int BN>
__device__ __forceinline__ void load_chunk(int tid, uint32_t base,
    const __nv_bfloat16* __restrict__ Ahi, const __nv_bfloat16* __restrict__ Alo,
    const __nv_bfloat16* __restrict__ Bhi, const __nv_bfloat16* __restrict__ Blo,
    int k0) {
    constexpr int A_BYTES = 128 * 128;
    constexpr int B_BYTES = BN * 128;
    constexpr int LITER = (8 * (256 + 2 * BN)) / 256;
#pragma unroll
    for (int it = 0; it < LITER; it++) {
        int idx = tid + it * 256;
        int seg = idx & 7, q = idx >> 3;
        const __nv_bfloat16* src;
        uint32_t toff;
        int r;
        if (q < 128)            { src = Ahi; toff = 0;                      r = q; }
        else if (q < 256)       { src = Alo; toff = A_BYTES;                r = q - 128; }
        else if (q < 256 + BN)  { src = Bhi; toff = 2 * A_BYTES;            r = q - 256; }
        else                    { src = Blo; toff = 2 * A_BYTES + B_BYTES;  r = q - 256 - BN; }
        uint32_t bo = r * 128 + seg * 16;
        uint32_t dst = base + toff + sw128(bo);
        const void* g = (const void*)(src + (size_t)r * 512 + k0 + seg * 8);
        CP_ASYNC16(dst, g);
    }
}

template<int BN>
__global__ void __launch_bounds__(256, 1)
mma_gemm_kernel(const __nv_bfloat16* __restrict__ Ahi, const __nv_bfloat16* __restrict__ Alo,
                const __nv_bfloat16* __restrict__ BhiBase, const __nv_bfloat16* __restrict__ BloBase,
                const float* __restrict__ biasBase, float* __restrict__ outBase, int Ntot) {
    constexpr int NC = 8;                          // K chunks of 64 bf16
    constexpr int A_BYTES = 128 * 128;
    constexpr int B_BYTES = BN * 128;
    constexpr int STAGE = 2 * A_BYTES + 2 * B_BYTES;
    constexpr int WN = BN / 2;                     // warp N extent
    constexpr int NF = WN / 8;                     // 8 for BN=128, 4 for BN=64

    extern __shared__ char smem[];
    const uint32_t tiles = smem_u32(smem);

    const int s = blockIdx.z;
    const int nBlock = blockIdx.x * BN;
    const int mBlock = blockIdx.y * 128;
    const __nv_bfloat16* Ahi_t = Ahi + (size_t)mBlock * 512;
    const __nv_bfloat16* Alo_t = Alo + (size_t)mBlock * 512;
    const __nv_bfloat16* Bhi_t = BhiBase + ((size_t)s * Ntot + nBlock) * 512;
    const __nv_bfloat16* Blo_t = BloBase + ((size_t)s * Ntot + nBlock) * 512;
    const float* bias = biasBase + s * Ntot + nBlock;

    const int tid = threadIdx.x;
    const int lane = tid & 31, w = tid >> 5;
    const int wm = (w & 3) * 32;                   // warp M offset
    const int wn = (w >> 2) * WN;                  // warp N offset

    float acc[2][NF][4];
#pragma unroll
    for (int mf = 0; mf < 2; mf++)
#pragma unroll
        for (int nf = 0; nf < NF; nf++)
#pragma unroll
            for (int i = 0; i < 4; i++) acc[mf][nf][i] = 0.f;

    // precomputed (lane-dependent) intra-tile offsets
    const uint32_t aRow = (uint32_t)(wm + (lane & 15));            // + mf*16
    const uint32_t aCol = (uint32_t)((lane >> 4) * 16);            // byte offset within row
    const uint32_t bRow = (uint32_t)(wn + ((lane >> 4) & 1) * 8 + (lane & 7));  // + nf2*16
    const uint32_t bCol = (uint32_t)(((lane >> 3) & 1) * 16);

    // prologue: chunk 0
    load_chunk<BN>(tid, tiles, Ahi_t, Alo_t, Bhi_t, Blo_t, 0);
    CP_COMMIT();

    for (int ck = 0; ck < NC; ck++) {
        const int nx = ck + 1;
        if (nx < NC) {
            load_chunk<BN>(tid, tiles + (nx & 1) * STAGE, Ahi_t, Alo_t, Bhi_t, Blo_t, nx * 64);
            CP_COMMIT();
            CP_WAIT(1);
        } else {
            CP_WAIT(0);
        }
        __syncthreads();

        const uint32_t aH = tiles + (ck & 1) * STAGE;
        const uint32_t aL = aH + A_BYTES;
        const uint32_t bH = aH + 2 * A_BYTES;
        const uint32_t bL = bH + B_BYTES;

#pragma unroll
        for (int k16 = 0; k16 < 4; k16++) {
            uint32_t fa_h[2][4], fa_l[2][4];
#pragma unroll
            for (int mf = 0; mf < 2; mf++) {
                uint32_t bo = (aRow + mf * 16) * 128 + (uint32_t)(k16 * 32) + aCol;
                ldsm_x4(fa_h[mf], aH + sw128(bo));
                ldsm_x4(fa_l[mf], aL + sw128(bo));
            }
            uint32_t fb_h[NF][2], fb_l[NF][2];
#pragma unroll
            for (int nf2 = 0; nf2 < NF / 2; nf2++) {
                uint32_t bo = (bRow + nf2 * 16) * 128 + (uint32_t)(k16 * 32) + bCol;
                uint32_t r[4];
                ldsm_x4(r, bH + sw128(bo));
                fb_h[2*nf2][0] = r[0]; fb_h[2*nf2][1] = r[1];
                fb_h[2*nf2+1][0] = r[2]; fb_h[2*nf2+1][1] = r[3];
                ldsm_x4(r, bL + sw128(bo));
                fb_l[2*nf2][0] = r[0]; fb_l[2*nf2][1] = r[1];
                fb_l[2*nf2+1][0] = r[2]; fb_l[2*nf2+1][1] = r[3];
            }
#pragma unroll
            for (int mf = 0; mf < 2; mf++)
#pragma unroll
                for (int nf = 0; nf < NF; nf++) {
                    mma16816(acc[mf][nf], fa_h[mf], fb_h[nf]);   // Ah*Bh
                    mma16816(acc[mf][nf], fa_h[mf], fb_l[nf]);   // Ah*Bl
                    mma16816(acc[mf][nf], fa_l[mf], fb_h[nf]);   // Al*Bh
                }
        }
        __syncthreads();
    }

    // epilogue: d0,d1 -> (row m + lane/4, cols +0,+1); d2,d3 -> row +8
#pragma unroll
    for (int mf = 0; mf < 2; mf++) {
        int m0 = mBlock + wm + mf * 16 + (lane >> 2);
#pragma unroll
        for (int rr = 0; rr < 2; rr++) {
            int m = m0 + rr * 8;                   // m = b*T + t
            int t = m & (Tt - 1), b = m >> 11;
            float* orow = outBase + ((size_t)(t * Bb + b) * Ss + s) * Ntot + nBlock;
#pragma unroll
            for (int nf = 0; nf < NF; nf++) {
                int col = wn + nf * 8 + (lane & 3) * 2;
                float2 v;
                v.x = acc[mf][nf][2 * rr]     + bias[col];
                v.y = acc[mf][nf][2 * rr + 1] + bias[col + 1];
                *(float2*)&orow[col] = v;
            }
        }
    }
}

// ---------------- seb: state_embed @ gate_W1[513:521] ----------------
__global__ void seb_kernel(const float* __restrict__ gate_W1,
                           const float* __restrict__ state_embed) {
    int i = blockIdx.x * blockDim.x + threadIdx.x;
    if (i >= 3 * Ss * GHh) return;
    int h = i % GHh;
    int s = (i / GHh) % Ss;
    int st = i / (GHh * Ss);
    float acc = 0.f;
#pragma unroll
    for (int e = 0; e < 8; e++)
        acc += state_embed[st * 8 + e] * gate_W1[((size_t)s * 521 + 513 + e) * GHh + h];
    g_seb[i] = acc;
}

// ---------------- err[t][b][s] = ||pred[t-1] - h[t]|| ----------------
__global__ void err_kernel(const float* __restrict__ h) {
    int t = blockIdx.x, b = blockIdx.y;
    int tid = threadIdx.x;
    if (t == 0) { if (tid < Ss) g_err[b * Ss + tid] = 0.f; return; }
    float4 hh = *(const float4*)&h[((long)b * Tt + t) * Dd + tid * 4];
    __shared__ float red[4];
    int lane = tid & 31, w = tid >> 5;
    for (int s = 0; s < Ss; s++) {
        const float4* pv =
            (const float4*)&g_preds[(((long)(t-1) * Bb + b) * Ss + s) * Dd];
        float4 p = pv[tid];
        float dx = p.x - hh.x, dy = p.y - hh.y, dz = p.z - hh.z, dw = p.w - hh.w;
        float a = dx*dx + dy*dy + dz*dz + dw*dw;
#pragma unroll
        for (int o = 16; o > 0; o >>= 1) a += __shfl_xor_sync(0xffffffffu, a, o);
        if (lane == 0) red[w] = a;
        __syncthreads();
        if (tid == 0) {
            float tot = red[0] + red[1] + red[2] + red[3];
            g_err[(t * Bb + b) * Ss + s] = sqrtf(tot + 1e-8f);
        }
        __syncthreads();
    }
}

__global__ void em_kernel() {
    int t = blockIdx.x, lane = threadIdx.x;
    float e = g_err[t * 32 + lane];
#pragma unroll
    for (int o = 4; o < 32; o <<= 1) e += __shfl_xor_sync(0xffffffffu, e, o);
    if (lane < Ss) g_em[t * Ss + lane] = e * 0.125f;
}

__global__ void mu_chain() {
    int s = threadIdx.x; if (s >= Ss) return;
    float mu = 0.f;
#pragma unroll 8
    for (int t = 0; t < Tt; t++) {
        g_mu[t * Ss + s] = mu;
        float e = g_em[t * Ss + s];
        if (t > 0) mu = 0.99f * mu + 0.01f * e;
    }
}

__global__ void dev_kernel() {
    int t = blockIdx.x, lane = threadIdx.x;
    int s = lane & 3;
    float e = g_err[t * 32 + lane];
    float d = fabsf(e - g_mu[t * Ss + s]);
#pragma unroll
    for (int o = 4; o < 32; o <<= 1) d += __shfl_xor_sync(0xffffffffu, d, o);
    if (lane < Ss) g_dv[t * Ss + lane] = d * 0.125f;
}

__global__ void sigma_chain() {
    int s = threadIdx.x; if (s >= Ss) return;
    float sg = 1.f;
#pragma unroll 8
    for (int t = 0; t < Tt; t++) {
        g_sig[t * Ss + s] = sg;
        float d = g_dv[t * Ss + s];
        if (t > 0) sg = 0.99f * sg + 0.01f * d;
    }
}

__global__ void gall_kernel(const float* __restrict__ gate_W1,
                            const float* __restrict__ gate_W2,
                            const float* __restrict__ gate_b2) {
    int t = blockIdx.x, b = blockIdx.y;
    int w = threadIdx.x >> 5, lane = threadIdx.x & 31;
    int st = w >> 2, s = w & 3;
    long row = ((long)t * Bb + b) * Ss + s;
    float z = (g_err[row] - g_mu[t * Ss + s]) / fmaxf(g_sig[t * Ss + s], 1e-3f);
    const float* hp = &g_hpart[row * GHh];
    float w1z0 = gate_W1[((size_t)s * 521 + 512) * GHh + lane];
    float w1z1 = gate_W1[((size_t)s * 521 + 512) * GHh + lane + 32];
    const float* seb = &g_seb[(st * Ss + s) * GHh];
    float v0 = hp[lane]      + z * w1z0 + seb[lane];
    float v1 = hp[lane + 32] + z * w1z1 + seb[lane + 32];
    float a = fmaxf(v0, 0.f) * gate_W2[s * GHh + lane]
            + fmaxf(v1, 0.f) * gate_W2[s * GHh + lane + 32];
#pragma unroll
    for (int o = 16; o > 0; o >>= 1) a += __shfl_xor_sync(0xffffffffu, a, o);
    if (lane == 0) {
        float x = a + gate_b2[s];
        g_gall[(size_t)st * (Tt * Bb * Ss) + row] = 1.f / (1.f + expf(-x));
    }
}

__global__ void gmean_kernel() {
    int t = blockIdx.x, st = blockIdx.y, lane = threadIdx.x;
    float g = g_gall[(size_t)st * (Tt * Bb * Ss) + t * 32 + lane];
#pragma unroll
    for (int o = 4; o < 32; o <<= 1) g += __shfl_xor_sync(0xffffffffu, g, o);
    if (lane < Ss) g_gmean[st * Tt * Ss + t * Ss + lane] = g * 0.125f;
}

__global__ void gate_chain() {
    int s = threadIdx.x; if (s >= Ss) return;
    float ema = 0.5f; int st = 0;
#pragma unroll 4
    for (int t = 0; t < Tt; t++) {
        g_state[t * Ss + s] = st;
        float g0 = g_gmean[0 * Tt * Ss + t * Ss + s];
        float g1 = g_gmean[1 * Tt * Ss + t * Ss + s];
        float g2 = g_gmean[2 * Tt * Ss + t * Ss + s];
        float gm = (st == 0) ? g0 : ((st == 1) ? g1 : g2);
        ema = 0.99f * ema + 0.01f * gm;
        int ns = st;
        if (st == 0) { if (ema < 0.1f) ns = 1; }
        else if (st == 1) { if (ema < 0.03f) ns = 2; else if (ema > 0.25f) ns = 0; }
        else { if (ema > 0.25f) ns = 0; }
        st = ns;
    }
}

__global__ void ge_kernel() {
    int t = blockIdx.x, lane = threadIdx.x;
    int s = lane & 3;
    int st = g_state[t * Ss + s];
    float gain = (st == 0) ? 1.0f : ((st == 1) ? 0.5f : 0.1f);
    g_ge[t * 32 + lane] = g_gall[(size_t)st * (Tt * Bb * Ss) + t * 32 + lane] * gain;
}

__global__ void mscan_kernel(const float* __restrict__ w0, float* __restrict__ out) {
    int bid = blockIdx.x;                 // 8*4*4 = 128
    int chunk = bid & 3, s = (bid >> 2) & 3, b = bid >> 4;
    int lane = threadIdx.x;
    int d = chunk * 128 + lane * 4;
    float4 m = *(const float4*)&w0[s * Dd + d];
    const float* gep = &g_ge[b * 4 + s];
    const float4* wp = (const float4*)&g_wenc[((long)b * Ss + s) * Dd + d];
    float4* op = (float4*)&out[((long)b * Tt) * (Ss * Dd) + s * Dd + d];
    const long wstride = (long)Bb * Ss * Dd / 4;
    const long ostride = Ss * Dd / 4;
#pragma unroll 4
    for (int t = 0; t < Tt; t++) {
        float ge = __ldg(&gep[t * 32]);
        float om = 1.f - ge;
        float4 w = wp[t * wstride];
        m.x = om * m.x + ge * w.x;
        m.y = om * m.y + ge * w.y;
        m.z = om * m.z + ge * w.z;
        m.w = om * m.w + ge * w.w;
        op[t * ostride] = m;
    }
}

// ---------------- launch ----------------
extern "C" void kernel_launch(void* const* d_in, const int* in_sizes, int n_in,
                              void* d_out, int out_size) {
    const float* h_seq       = (const float*)d_in[0];
    const float* pred_W      = (const float*)d_in[1];
    const float* pred_b      = (const float*)d_in[2];
    const float* gate_W1     = (const float*)d_in[3];
    const float* gate_b1     = (const float*)d_in[4];
    const float* gate_W2     = (const float*)d_in[5];
    const float* gate_b2     = (const float*)d_in[6];
    const float* write_W     = (const float*)d_in[7];
    const float* write_b     = (const float*)d_in[8];
    const float* w0          = (const float*)d_in[9];
    const float* state_embed = (const float*)d_in[10];
    float* out = (float*)d_out;

    float *p_preds, *p_wenc, *p_hpart;
    cudaGetSymbolAddress((void**)&p_preds, g_preds);
    cudaGetSymbolAddress((void**)&p_wenc,  g_wenc);
    cudaGetSymbolAddress((void**)&p_hpart, g_hpart);
    __nv_bfloat16 *pAhi, *pAlo, *pPWhi, *pPWlo, *pWWhi, *pWWlo, *pGWhi, *pGWlo;
    cudaGetSymbolAddress((void**)&pAhi,  g_Ahi);
    cudaGetSymbolAddress((void**)&pAlo,  g_Alo);
    cudaGetSymbolAddress((void**)&pPWhi, g_PWhi);
    cudaGetSymbolAddress((void**)&pPWlo, g_PWlo);
    cudaGetSymbolAddress((void**)&pWWhi, g_WWhi);
    cudaGetSymbolAddress((void**)&pWWlo, g_WWlo);
    cudaGetSymbolAddress((void**)&pGWhi, g_GWhi);
    cudaGetSymbolAddress((void**)&pGWlo, g_GWlo);

    constexpr int SMEM128 = 2 * (2 * 128 * 128 + 2 * 128 * 128);  // 131072
    constexpr int SMEM64  = 2 * (2 * 128 * 128 + 2 * 64 * 128);   //  98304
    cudaFuncSetAttribute(mma_gemm_kernel<128>, cudaFuncAttributeMaxDynamicSharedMemorySize, SMEM128);
    cudaFuncSetAttribute(mma_gemm_kernel<64>,  cudaFuncAttributeMaxDynamicSharedMemorySize, SMEM64);

    // conversions
    convert_h_kernel<<<(Bb * Tt * Dd) / 256, 256>>>(h_seq, pAhi, pAlo);
    transpose_conv_kernel<<<dim3(16, 16, 4), dim3(32, 8)>>>(pred_W,  (long)Dd * Dd, Dd,  pPWhi, pPWlo);
    transpose_conv_kernel<<<dim3(16, 16, 4), dim3(32, 8)>>>(write_W, (long)Dd * Dd, Dd,  pWWhi, pWWlo);
    transpose_conv_kernel<<<dim3(2,  16, 4), dim3(32, 8)>>>(gate_W1, (long)521 * GHh, GHh, pGWhi, pGWlo);
    seb_kernel<<<3, 256>>>(gate_W1, state_embed);

    // tensor-core GEMMs (mma.sync bf16 hi/lo)
    dim3 gBig(Dd / 128, (Bb * Tt) / 128, Ss);
    mma_gemm_kernel<128><<<gBig, 256, SMEM128>>>(pAhi, pAlo, pPWhi, pPWlo, pred_b,  p_preds, Dd);
    mma_gemm_kernel<128><<<gBig, 256, SMEM128>>>(pAhi, pAlo, pWWhi, pWWlo, write_b, p_wenc,  Dd);
    dim3 gGate(1, (Bb * Tt) / 128, Ss);
    mma_gemm_kernel<64><<<gGate, 256, SMEM64>>>(pAhi, pAlo, pGWhi, pGWlo, gate_b1, p_hpart, GHh);

    // sequential-lite tail
    err_kernel<<<dim3(Tt, Bb), 128>>>(h_seq);
    em_kernel<<<Tt, 32>>>();
    mu_chain<<<1, 32>>>();
    dev_kernel<<<Tt, 32>>>();
    sigma_chain<<<1, 32>>>();
    gall_kernel<<<dim3(Tt, Bb), 384>>>(gate_W1, gate_W2, gate_b2);
    gmean_kernel<<<dim3(Tt, 3), 32>>>();
    gate_chain<<<1, 32>>>();
    ge_kernel<<<Tt, 32>>>();
    mscan_kernel<<<128, 32>>>(w0, out);
}